// round 1
// baseline (speedup 1.0000x reference)
#include <cuda_runtime.h>
#include <math.h>
#include <stdint.h>

// Problem dims
#define HH   512
#define BB   256
#define SS   64
#define VV   32000
#define SB   (SS*BB)     // 16384
#define G4H  (4*HH)      // 2048
#define H2   (2*HH)      // 1024
#define G8H  (8*HH)      // 4096

// ------------------------- device scratch (no allocs) -------------------------
__device__ float g_seq [SB * HH];            // (16384, 512)   32 MB
__device__ float g_Xf  [SB * G4H];           // (16384, 2048) 128 MB
__device__ float g_Xb  [SB * G4H];           // 128 MB
__device__ float g_comb[SB * H2];            // (16384, 1024)  64 MB
__device__ float g_Xc  [(size_t)SB * G8H];   // (16384, 4096) 256 MB
__device__ float g_gf  [BB * G4H];
__device__ float g_gb  [BB * G4H];
__device__ float g_gc  [BB * G8H];
__device__ float g_hf[BB*HH], g_cf[BB*HH], g_hb[BB*HH], g_cb[BB*HH];
__device__ float g_hc[BB*H2], g_cc[BB*H2];

// ------------------------- embedding ------------------------------------------
// seq[r][:] = (tok==0) ? 0 : W_emb[tok][:],  tok = x_flat[r]  (raw reshape semantics)
__global__ void embed_kernel(const int* __restrict__ x, const float* __restrict__ Wemb) {
    int r = blockIdx.x;                 // 0..SB-1
    int tok = x[r];
    float4* dst = (float4*)(g_seq + (size_t)r * HH);
    int t = threadIdx.x;                // 128 threads, HH/4 = 128 float4
    if (tok == 0) {
        dst[t] = make_float4(0.f, 0.f, 0.f, 0.f);
    } else {
        const float4* src = (const float4*)(Wemb + (size_t)tok * HH);
        dst[t] = src[t];
    }
}

// ------------------------- init recurrent states ------------------------------
__global__ void init_states(const float* h0f, const float* c0f,
                            const float* h0b, const float* c0b,
                            const float* h0c, const float* c0c) {
    int i = blockIdx.x * blockDim.x + threadIdx.x;
    if (i < BB * HH) {
        g_hf[i] = h0f[i]; g_cf[i] = c0f[i];
        g_hb[i] = h0b[i]; g_cb[i] = c0b[i];
    }
    if (i < BB * H2) {
        g_hc[i] = h0c[i]; g_cc[i] = c0c[i];
    }
}

// ------------------------- generic fp32 NT GEMM -------------------------------
// C[m][n] = sum_k A[m][k] * B[n][k]  (+ Cadd[m][n]) (+ bias0[n]) (+ bias1[n])
// A row-major (lda=K stride), B row-major (ldb=K stride), C row-major ldc.
// Requires M % BM == 0, N % BN == 0, K % 16 == 0 (true for all shapes here).
template<int BM, int BN>
__global__ __launch_bounds__((BM/8)*(BN/8))
void gemm_nt(const float* __restrict__ A, int lda,
             const float* __restrict__ Bmat, int ldb,
             const float* __restrict__ Cadd,
             const float* __restrict__ bias0,
             const float* __restrict__ bias1,
             float* __restrict__ C, int ldc,
             int K)
{
    constexpr int BK = 16;
    constexpr int TX = BN / 8;
    constexpr int TY = BM / 8;
    constexpr int NT = TX * TY;

    __shared__ float As[BK][BM + 4];
    __shared__ float Bs[BK][BN + 4];

    const int tid = threadIdx.x;
    const int tx  = tid % TX;
    const int ty  = tid / TX;
    const int row0 = blockIdx.y * BM;
    const int col0 = blockIdx.x * BN;

    float acc[8][8];
    #pragma unroll
    for (int i = 0; i < 8; i++)
        #pragma unroll
        for (int j = 0; j < 8; j++) acc[i][j] = 0.f;

    const float* Ab = A    + (size_t)row0 * lda;
    const float* Bb = Bmat + (size_t)col0 * ldb;

    for (int k0 = 0; k0 < K; k0 += BK) {
        // load A tile (BM x 16), store transposed As[k][m]
        #pragma unroll
        for (int q = tid; q < BM * 4; q += NT) {
            int r  = q >> 2;
            int c4 = (q & 3) * 4;
            float4 v = *(const float4*)(Ab + (size_t)r * lda + k0 + c4);
            As[c4 + 0][r] = v.x; As[c4 + 1][r] = v.y;
            As[c4 + 2][r] = v.z; As[c4 + 3][r] = v.w;
        }
        // load B tile (BN x 16), store transposed Bs[k][n]
        #pragma unroll
        for (int q = tid; q < BN * 4; q += NT) {
            int r  = q >> 2;
            int c4 = (q & 3) * 4;
            float4 v = *(const float4*)(Bb + (size_t)r * ldb + k0 + c4);
            Bs[c4 + 0][r] = v.x; Bs[c4 + 1][r] = v.y;
            Bs[c4 + 2][r] = v.z; Bs[c4 + 3][r] = v.w;
        }
        __syncthreads();

        #pragma unroll
        for (int kk = 0; kk < BK; kk++) {
            float a[8], b[8];
            #pragma unroll
            for (int i = 0; i < 8; i++) a[i] = As[kk][ty * 8 + i];
            #pragma unroll
            for (int j = 0; j < 8; j++) b[j] = Bs[kk][tx * 8 + j];
            #pragma unroll
            for (int i = 0; i < 8; i++)
                #pragma unroll
                for (int j = 0; j < 8; j++)
                    acc[i][j] = fmaf(a[i], b[j], acc[i][j]);
        }
        __syncthreads();
    }

    #pragma unroll
    for (int i = 0; i < 8; i++) {
        int m = row0 + ty * 8 + i;
        #pragma unroll
        for (int j = 0; j < 8; j++) {
            int n = col0 + tx * 8 + j;
            float v = acc[i][j];
            if (Cadd)  v += Cadd[(size_t)m * ldc + n];
            if (bias0) v += bias0[n];
            if (bias1) v += bias1[n];
            C[(size_t)m * ldc + n] = v;
        }
    }
}

// ------------------------- gate nonlinearities --------------------------------
__device__ __forceinline__ float sigmoidf_(float x) {
    return 1.f / (1.f + expf(-x));
}

// fused fwd + bwd cell update at iteration s; writes h into comb_in[s]
__global__ void gates_fb(int s) {
    int idx = blockIdx.x * blockDim.x + threadIdx.x;   // 2*BB*HH threads
    int cell = idx / (BB * HH);
    int rem  = idx % (BB * HH);
    int b = rem / HH, j = rem % HH;

    const float* g = cell ? g_gb : g_gf;
    float* hs = cell ? g_hb : g_hf;
    float* cs = cell ? g_cb : g_cf;

    float i_ = sigmoidf_(g[(size_t)b * G4H + j]);
    float f_ = sigmoidf_(g[(size_t)b * G4H + HH + j]);
    float gg = tanhf    (g[(size_t)b * G4H + 2 * HH + j]);
    float o_ = sigmoidf_(g[(size_t)b * G4H + 3 * HH + j]);

    float cn = f_ * cs[b * HH + j] + i_ * gg;
    float hn = o_ * tanhf(cn);
    cs[b * HH + j] = cn;
    hs[b * HH + j] = hn;
    // fwd -> cols [0,512), bwd -> cols [512,1024) of comb_in row s*BB+b
    g_comb[(size_t)(s * BB + b) * H2 + cell * HH + j] = hn;
}

// combiner cell update
__global__ void gates_c() {
    int idx = blockIdx.x * blockDim.x + threadIdx.x;   // BB*H2 threads
    int b = idx / H2, j = idx % H2;

    float i_ = sigmoidf_(g_gc[(size_t)b * G8H + j]);
    float f_ = sigmoidf_(g_gc[(size_t)b * G8H + H2 + j]);
    float gg = tanhf    (g_gc[(size_t)b * G8H + 2 * H2 + j]);
    float o_ = sigmoidf_(g_gc[(size_t)b * G8H + 3 * H2 + j]);

    float cn = f_ * g_cc[idx] + i_ * gg;
    float hn = o_ * tanhf(cn);
    g_cc[idx] = cn;
    g_hc[idx] = hn;
}

// ------------------------- host orchestration ---------------------------------
extern "C" void kernel_launch(void* const* d_in, const int* in_sizes, int n_in,
                              void* d_out, int out_size) {
    (void)in_sizes; (void)n_in; (void)out_size;

    const int*   x     = (const int*)  d_in[0];
    const float* Wemb  = (const float*)d_in[1];
    const float* Wih_f = (const float*)d_in[2];
    const float* Whh_f = (const float*)d_in[3];
    const float* bih_f = (const float*)d_in[4];
    const float* bhh_f = (const float*)d_in[5];
    const float* Wih_b = (const float*)d_in[6];
    const float* Whh_b = (const float*)d_in[7];
    const float* bih_b = (const float*)d_in[8];
    const float* bhh_b = (const float*)d_in[9];
    const float* Wih_c = (const float*)d_in[10];
    const float* Whh_c = (const float*)d_in[11];
    const float* bih_c = (const float*)d_in[12];
    const float* bhh_c = (const float*)d_in[13];
    const float* Wout  = (const float*)d_in[14];
    const float* bout  = (const float*)d_in[15];
    const float* h0f   = (const float*)d_in[16];
    const float* c0f   = (const float*)d_in[17];
    const float* h0b   = (const float*)d_in[18];
    const float* c0b   = (const float*)d_in[19];
    const float* h0c   = (const float*)d_in[20];
    const float* c0c   = (const float*)d_in[21];
    float* out = (float*)d_out;

    float *p_seq, *p_Xf, *p_Xb, *p_comb, *p_Xc, *p_gf, *p_gb, *p_gc, *p_hf, *p_hb, *p_hc;
    cudaGetSymbolAddress((void**)&p_seq,  g_seq);
    cudaGetSymbolAddress((void**)&p_Xf,   g_Xf);
    cudaGetSymbolAddress((void**)&p_Xb,   g_Xb);
    cudaGetSymbolAddress((void**)&p_comb, g_comb);
    cudaGetSymbolAddress((void**)&p_Xc,   g_Xc);
    cudaGetSymbolAddress((void**)&p_gf,   g_gf);
    cudaGetSymbolAddress((void**)&p_gb,   g_gb);
    cudaGetSymbolAddress((void**)&p_gc,   g_gc);
    cudaGetSymbolAddress((void**)&p_hf,   g_hf);
    cudaGetSymbolAddress((void**)&p_hb,   g_hb);
    cudaGetSymbolAddress((void**)&p_hc,   g_hc);

    // 1) embedding (raw-reshape order) + state init
    embed_kernel<<<SB, 128>>>(x, Wemb);
    init_states<<<(BB * H2 + 255) / 256, 256>>>(h0f, c0f, h0b, c0b, h0c, c0c);

    // 2) input projections: Xf/Xb = seq @ Wih^T + (bih + bhh)
    gemm_nt<128,128><<<dim3(G4H/128, SB/128), 256>>>(
        p_seq, HH, Wih_f, HH, nullptr, bih_f, bhh_f, p_Xf, G4H, HH);
    gemm_nt<128,128><<<dim3(G4H/128, SB/128), 256>>>(
        p_seq, HH, Wih_b, HH, nullptr, bih_b, bhh_b, p_Xb, G4H, HH);

    // 3) fwd + bwd recurrences (bwd consumes seq reversed; outputs in produced order)
    for (int s = 0; s < SS; s++) {
        gemm_nt<64,128><<<dim3(G4H/128, BB/64), 128>>>(
            p_hf, HH, Whh_f, HH, p_Xf + (size_t)s * BB * G4H,
            nullptr, nullptr, p_gf, G4H, HH);
        gemm_nt<64,128><<<dim3(G4H/128, BB/64), 128>>>(
            p_hb, HH, Whh_b, HH, p_Xb + (size_t)(SS - 1 - s) * BB * G4H,
            nullptr, nullptr, p_gb, G4H, HH);
        gates_fb<<<(2 * BB * HH) / 256, 256>>>(s);
    }

    // 4) combiner input projection: Xc = comb_in @ Wih_c^T + (bih_c + bhh_c)
    gemm_nt<128,128><<<dim3(G8H/128, SB/128), 256>>>(
        p_comb, H2, Wih_c, H2, nullptr, bih_c, bhh_c, p_Xc, G8H, H2);

    // 5) combiner recurrence
    for (int s = 0; s < SS; s++) {
        gemm_nt<64,128><<<dim3(G8H/128, BB/64), 128>>>(
            p_hc, H2, Whh_c, H2, p_Xc + (size_t)s * BB * G8H,
            nullptr, nullptr, p_gc, G8H, H2);
        gates_c<<<(BB * H2) / 256, 256>>>();
    }

    // 6) head: out = hc_last @ Wout^T + bout
    gemm_nt<128,128><<<dim3(VV/128, BB/128), 256>>>(
        p_hc, H2, Wout, H2, nullptr, bout, nullptr, out, VV, H2);
}

// round 5
// speedup vs baseline: 1.8443x; 1.8443x over previous
#include <cuda_runtime.h>
#include <cuda_bf16.h>
#include <math.h>
#include <stdint.h>
#include <string.h>

#define HH   512
#define BB   256
#define SS   64
#define VV   32000
#define SB   (SS*BB)     // 16384
#define G4H  (4*HH)      // 2048
#define H2   (2*HH)      // 1024
#define G8H  (8*HH)      // 4096

// ------------------------- device scratch (no allocs) -------------------------
__device__ __align__(16) __nv_bfloat16 g_seq_hi[SB*HH],  g_seq_lo[SB*HH];
__device__ __align__(16) __nv_bfloat16 g_comb_hi[SB*H2], g_comb_lo[SB*H2];
__device__ __align__(16) float g_Xf[SB*G4H];
__device__ __align__(16) float g_Xb[SB*G4H];
__device__ __align__(16) float g_Xc[(size_t)SB*G8H];
__device__ __align__(16) __nv_bfloat16 g_Wihf_hi[G4H*HH], g_Wihf_lo[G4H*HH];
__device__ __align__(16) __nv_bfloat16 g_Whhf_hi[G4H*HH], g_Whhf_lo[G4H*HH];
__device__ __align__(16) __nv_bfloat16 g_Wihb_hi[G4H*HH], g_Wihb_lo[G4H*HH];
__device__ __align__(16) __nv_bfloat16 g_Whhb_hi[G4H*HH], g_Whhb_lo[G4H*HH];
__device__ __align__(16) __nv_bfloat16 g_Wihc_hi[G8H*H2], g_Wihc_lo[G8H*H2];
__device__ __align__(16) __nv_bfloat16 g_Whhc_hi[G8H*H2], g_Whhc_lo[G8H*H2];
__device__ __align__(16) __nv_bfloat16 g_Wout_hi[VV*H2],  g_Wout_lo[VV*H2];
__device__ __align__(16) float g_bfb[G4H], g_bbb[G4H], g_bcb[G8H];
// ping-pong recurrent h states (buffer = step parity), single-buffer c states
__device__ __align__(16) __nv_bfloat16 g_hf_hi[2][BB*HH], g_hf_lo[2][BB*HH];
__device__ __align__(16) __nv_bfloat16 g_hb_hi[2][BB*HH], g_hb_lo[2][BB*HH];
__device__ __align__(16) __nv_bfloat16 g_hc_hi[2][BB*H2], g_hc_lo[2][BB*H2];
__device__ __align__(16) float g_cf[BB*HH], g_cb[BB*HH], g_cc[BB*H2];

// ------------------------- helpers --------------------------------------------
__device__ __forceinline__ uint32_t s2u(const void* p){
    uint32_t a;
    asm("{ .reg .u64 t; cvta.to.shared.u64 t, %1; cvt.u32.u64 %0, t; }" : "=r"(a) : "l"(p));
    return a;
}
#define LDMX4(r, addr) \
    asm volatile("ldmatrix.sync.aligned.m8n8.x4.shared.b16 {%0,%1,%2,%3}, [%4];" \
        : "=r"((r)[0]), "=r"((r)[1]), "=r"((r)[2]), "=r"((r)[3]) : "r"(addr))
#define MMA16816(c, A, Bv) \
    asm volatile("mma.sync.aligned.m16n8k16.row.col.f32.bf16.bf16.f32 " \
        "{%0,%1,%2,%3}, {%4,%5,%6,%7}, {%8,%9}, {%0,%1,%2,%3};" \
        : "+f"((c)[0]), "+f"((c)[1]), "+f"((c)[2]), "+f"((c)[3]) \
        : "r"((A)[0]), "r"((A)[1]), "r"((A)[2]), "r"((A)[3]), "r"((Bv)[0]), "r"((Bv)[1]))
#define CPASYNC16(dst, src) \
    asm volatile("cp.async.cg.shared.global [%0], [%1], 16;" :: "r"(dst), "l"(src))

// ------------------------- unified HMMA GEMM kernel ----------------------------
// D[128x128] = 3-term bf16-split GEMM (Ahi*Bhi + Ahi*Blo + Alo*Bhi), fp32 acc.
// plain:  C[r][n0+n] = D + bias[n0+n]
// gated:  B rows gathered so col n -> (gate n&3, j = bx*32 + n>>2); fused LSTM.
struct GArgs {
    const __nv_bfloat16 *Ahi, *Alo;
    const __nv_bfloat16 *Bhi, *Blo;
    const float* bias;
    float* C;
    int ldc;
    const float* X;
    float* cst;
    __nv_bfloat16 *Hhi, *Hlo;         // write targets (next-parity buffers)
    __nv_bfloat16 *CBhi, *CBlo;
    long combRow;
    int combCol;
    int K;                 // 512 or 1024 (K % 64 == 0, K/64 >= 3)
};
struct GArgs2 { GArgs a[2]; };

#define RSB   144                  // smem row stride bytes (64 bf16 + 8 pad)
#define TILEB (128*RSB)            // 18432
#define STGB  (4*TILEB)            // 73728 per stage
#define NSTG  3
#define SMEM_DYN (NSTG*STGB)       // 221184

template<bool GATED>
__global__ __launch_bounds__(256, 1) void mma_gemm(GArgs2 P)
{
    const GArgs a = P.a[GATED ? blockIdx.z : 0];
    extern __shared__ char sm[];

    const int tid = threadIdx.x, lane = tid & 31, wid = tid >> 5;
    const int wm = wid & 1, wn = wid >> 1;         // warp tile: 64x32
    const int m0 = blockIdx.y << 7;
    const int bx = blockIdx.x;
    const int K  = a.K;
    const int KB = K >> 6;

    auto issue = [&](int kb){
        char* sb = sm + (kb % NSTG) * STGB;
        const int k0 = kb << 6;
        #pragma unroll
        for (int i = 0; i < 16; i++){
            const int tile = i >> 2;
            const int pos  = ((i & 3) << 8) + tid;   // 0..1023
            const int row  = pos >> 3;               // 0..127
            const int c8   = pos & 7;                // 16B chunk
            const __nv_bfloat16* src;
            if (tile == 0)      src = a.Ahi + (size_t)(m0 + row) * K + k0 + (c8 << 3);
            else if (tile == 1) src = a.Alo + (size_t)(m0 + row) * K + k0 + (c8 << 3);
            else {
                const int wrow = GATED ? ((row & 3) * K + (bx << 5) + (row >> 2))
                                       : ((bx << 7) + row);
                src = (tile == 2 ? a.Bhi : a.Blo) + (size_t)wrow * K + k0 + (c8 << 3);
            }
            uint32_t dst = s2u(sb + tile * TILEB + row * RSB + (c8 << 4));
            CPASYNC16(dst, src);
        }
        asm volatile("cp.async.commit_group;" ::: "memory");
    };

    float acc[4][4][4];
    #pragma unroll
    for (int mt = 0; mt < 4; mt++)
        #pragma unroll
        for (int nt = 0; nt < 4; nt++)
            #pragma unroll
            for (int q = 0; q < 4; q++) acc[mt][nt][q] = 0.f;

    issue(0); issue(1);

    for (int kb = 0; kb < KB; kb++){
        if (kb + 2 < KB) issue(kb + 2);
        if (kb == KB - 1)      asm volatile("cp.async.wait_group 0;" ::: "memory");
        else if (kb == KB - 2) asm volatile("cp.async.wait_group 1;" ::: "memory");
        else                   asm volatile("cp.async.wait_group 2;" ::: "memory");
        __syncthreads();

        char* sb = sm + (kb % NSTG) * STGB;
        const uint32_t bAh = s2u(sb);
        const uint32_t bBh = bAh + 2 * TILEB;

        #pragma unroll
        for (int k16 = 0; k16 < 4; k16++){
            uint32_t Ah[4][4], Al[4][4], Bh[4][2], Bl[4][2];
            const int kcbA = (k16 << 5) + (((lane >> 4) & 1) << 4);
            #pragma unroll
            for (int mt = 0; mt < 4; mt++){
                const int row = (wm << 6) + (mt << 4) + (lane & 15);
                const uint32_t ad = bAh + row * RSB + kcbA;
                LDMX4(Ah[mt], ad);
                LDMX4(Al[mt], ad + TILEB);
            }
            {
                const int rowb = (wn << 5) + (((lane >> 4) & 1) << 3) + (lane & 7);
                const int kcbB = (k16 << 5) + (((lane >> 3) & 1) << 4);
                const uint32_t bd0 = bBh + rowb * RSB + kcbB;      // nt 0,1
                const uint32_t bd1 = bd0 + 16 * RSB;               // nt 2,3
                uint32_t t[4];
                LDMX4(t, bd0); Bh[0][0]=t[0]; Bh[0][1]=t[1]; Bh[1][0]=t[2]; Bh[1][1]=t[3];
                LDMX4(t, bd1); Bh[2][0]=t[0]; Bh[2][1]=t[1]; Bh[3][0]=t[2]; Bh[3][1]=t[3];
                LDMX4(t, bd0 + TILEB); Bl[0][0]=t[0]; Bl[0][1]=t[1]; Bl[1][0]=t[2]; Bl[1][1]=t[3];
                LDMX4(t, bd1 + TILEB); Bl[2][0]=t[0]; Bl[2][1]=t[1]; Bl[3][0]=t[2]; Bl[3][1]=t[3];
            }
            #pragma unroll
            for (int mt = 0; mt < 4; mt++)
                #pragma unroll
                for (int nt = 0; nt < 4; nt++){
                    MMA16816(acc[mt][nt], Ah[mt], Bh[nt]);
                    MMA16816(acc[mt][nt], Ah[mt], Bl[nt]);
                    MMA16816(acc[mt][nt], Al[mt], Bh[nt]);
                }
        }
        __syncthreads();
    }

    // ------------------------------ epilogue ------------------------------
    const int g = lane >> 2, tig = lane & 3;
    if (!GATED){
        #pragma unroll
        for (int mt = 0; mt < 4; mt++){
            const int r = m0 + (wm << 6) + (mt << 4) + g;
            #pragma unroll
            for (int nt = 0; nt < 4; nt++){
                const int n = (bx << 7) + (wn << 5) + (nt << 3) + (tig << 1);
                const float b0 = a.bias[n], b1 = a.bias[n + 1];
                float* c0p = a.C + (size_t)r * a.ldc + n;
                float* c1p = a.C + (size_t)(r + 8) * a.ldc + n;
                c0p[0] = acc[mt][nt][0] + b0; c0p[1] = acc[mt][nt][1] + b1;
                c1p[0] = acc[mt][nt][2] + b0; c1p[1] = acc[mt][nt][3] + b1;
            }
        }
    } else {
        const bool odd = (tig & 1);
        #pragma unroll
        for (int mt = 0; mt < 4; mt++){
            #pragma unroll
            for (int nt = 0; nt < 4; nt++){
                float c0 = acc[mt][nt][0], c1 = acc[mt][nt][1];
                float c2 = acc[mt][nt][2], c3 = acc[mt][nt][3];
                float e0 = __shfl_xor_sync(0xFFFFFFFFu, odd ? c0 : c2, 1);
                float e1 = __shfl_xor_sync(0xFFFFFFFFu, odd ? c1 : c3, 1);
                const int r = m0 + (wm << 6) + (mt << 4) + g + (odd ? 8 : 0);
                const int j = (bx << 5) + (wn << 3) + (nt << 1) + (tig >> 1);
                float gi, gf, gg, go;
                if (odd){ gi = e0; gf = e1; gg = c2; go = c3; }
                else    { gi = c0; gf = c1; gg = e0; go = e1; }
                const float* Xrow = a.X + (size_t)r * (K << 2);
                gi += Xrow[j];
                gf += Xrow[K + j];
                gg += Xrow[2 * K + j];
                go += Xrow[3 * K + j];
                const float ii = 1.f / (1.f + expf(-gi));
                const float ff = 1.f / (1.f + expf(-gf));
                const float gt = tanhf(gg);
                const float oo = 1.f / (1.f + expf(-go));
                const size_t si = (size_t)r * K + j;
                const float cn = ff * a.cst[si] + ii * gt;
                const float hn = oo * tanhf(cn);
                a.cst[si] = cn;
                const __nv_bfloat16 hh = __float2bfloat16(hn);
                const __nv_bfloat16 hl = __float2bfloat16(hn - __bfloat162float(hh));
                a.Hhi[si] = hh; a.Hlo[si] = hl;
                if (a.CBhi){
                    const size_t ci = (size_t)(a.combRow + r) * H2 + a.combCol + j;
                    a.CBhi[ci] = hh; a.CBlo[ci] = hl;
                }
            }
        }
    }
}

// ------------------------- small prep kernels ---------------------------------
__global__ void split_pair_kernel(const float* __restrict__ src,
                                  __nv_bfloat16* __restrict__ hi,
                                  __nv_bfloat16* __restrict__ lo, int n){
    for (int i = blockIdx.x * blockDim.x + threadIdx.x; i < n; i += gridDim.x * blockDim.x){
        float v = src[i];
        __nv_bfloat16 h = __float2bfloat16(v);
        hi[i] = h;
        lo[i] = __float2bfloat16(v - __bfloat162float(h));
    }
}
__global__ void bias_add_kernel(const float* __restrict__ a, const float* __restrict__ b,
                                float* __restrict__ c, int n){
    int i = blockIdx.x * blockDim.x + threadIdx.x;
    if (i < n) c[i] = a[i] + b[i];
}
__global__ void embed_split_kernel(const int* __restrict__ x, const float* __restrict__ W){
    int r = blockIdx.x;
    int tok = x[r];
    for (int k = threadIdx.x; k < HH; k += blockDim.x){
        float v = tok ? W[(size_t)tok * HH + k] : 0.f;
        __nv_bfloat16 h = __float2bfloat16(v);
        g_seq_hi[(size_t)r * HH + k] = h;
        g_seq_lo[(size_t)r * HH + k] = __float2bfloat16(v - __bfloat162float(h));
    }
}
__global__ void init_states_kernel(const float* h0f, const float* c0f,
                                   const float* h0b, const float* c0b,
                                   const float* h0c, const float* c0c){
    int i = blockIdx.x * blockDim.x + threadIdx.x;
    if (i < BB * HH){
        float vf = h0f[i]; __nv_bfloat16 hf = __float2bfloat16(vf);
        g_hf_hi[0][i] = hf; g_hf_lo[0][i] = __float2bfloat16(vf - __bfloat162float(hf));
        g_cf[i] = c0f[i];
        float vb = h0b[i]; __nv_bfloat16 hb = __float2bfloat16(vb);
        g_hb_hi[0][i] = hb; g_hb_lo[0][i] = __float2bfloat16(vb - __bfloat162float(hb));
        g_cb[i] = c0b[i];
    }
    if (i < BB * H2){
        float vc = h0c[i]; __nv_bfloat16 hc = __float2bfloat16(vc);
        g_hc_hi[0][i] = hc; g_hc_lo[0][i] = __float2bfloat16(vc - __bfloat162float(hc));
        g_cc[i] = c0c[i];
    }
}

// ------------------------- host orchestration ---------------------------------
static void* sym(const void* s){ void* p; cudaGetSymbolAddress(&p, s); return p; }

extern "C" void kernel_launch(void* const* d_in, const int* in_sizes, int n_in,
                              void* d_out, int out_size) {
    (void)in_sizes; (void)n_in; (void)out_size;

    const int*   x     = (const int*)  d_in[0];
    const float* Wemb  = (const float*)d_in[1];
    const float* Wih_f = (const float*)d_in[2];
    const float* Whh_f = (const float*)d_in[3];
    const float* bih_f = (const float*)d_in[4];
    const float* bhh_f = (const float*)d_in[5];
    const float* Wih_b = (const float*)d_in[6];
    const float* Whh_b = (const float*)d_in[7];
    const float* bih_b = (const float*)d_in[8];
    const float* bhh_b = (const float*)d_in[9];
    const float* Wih_c = (const float*)d_in[10];
    const float* Whh_c = (const float*)d_in[11];
    const float* bih_c = (const float*)d_in[12];
    const float* bhh_c = (const float*)d_in[13];
    const float* Wout  = (const float*)d_in[14];
    const float* bout  = (const float*)d_in[15];
    const float* h0f   = (const float*)d_in[16];
    const float* c0f   = (const float*)d_in[17];
    const float* h0b   = (const float*)d_in[18];
    const float* c0b   = (const float*)d_in[19];
    const float* h0c   = (const float*)d_in[20];
    const float* c0c   = (const float*)d_in[21];
    float* out = (float*)d_out;

    cudaFuncSetAttribute(mma_gemm<false>, cudaFuncAttributeMaxDynamicSharedMemorySize, SMEM_DYN);
    cudaFuncSetAttribute(mma_gemm<true>,  cudaFuncAttributeMaxDynamicSharedMemorySize, SMEM_DYN);

    __nv_bfloat16 *seq_hi = (__nv_bfloat16*)sym(g_seq_hi), *seq_lo = (__nv_bfloat16*)sym(g_seq_lo);
    __nv_bfloat16 *cmb_hi = (__nv_bfloat16*)sym(g_comb_hi), *cmb_lo = (__nv_bfloat16*)sym(g_comb_lo);
    float *Xf = (float*)sym(g_Xf), *Xb = (float*)sym(g_Xb), *Xc = (float*)sym(g_Xc);
    __nv_bfloat16 *Wihf_hi=(__nv_bfloat16*)sym(g_Wihf_hi), *Wihf_lo=(__nv_bfloat16*)sym(g_Wihf_lo);
    __nv_bfloat16 *Whhf_hi=(__nv_bfloat16*)sym(g_Whhf_hi), *Whhf_lo=(__nv_bfloat16*)sym(g_Whhf_lo);
    __nv_bfloat16 *Wihb_hi=(__nv_bfloat16*)sym(g_Wihb_hi), *Wihb_lo=(__nv_bfloat16*)sym(g_Wihb_lo);
    __nv_bfloat16 *Whhb_hi=(__nv_bfloat16*)sym(g_Whhb_hi), *Whhb_lo=(__nv_bfloat16*)sym(g_Whhb_lo);
    __nv_bfloat16 *Wihc_hi=(__nv_bfloat16*)sym(g_Wihc_hi), *Wihc_lo=(__nv_bfloat16*)sym(g_Wihc_lo);
    __nv_bfloat16 *Whhc_hi=(__nv_bfloat16*)sym(g_Whhc_hi), *Whhc_lo=(__nv_bfloat16*)sym(g_Whhc_lo);
    __nv_bfloat16 *Wout_hi=(__nv_bfloat16*)sym(g_Wout_hi), *Wout_lo=(__nv_bfloat16*)sym(g_Wout_lo);
    float *bfb=(float*)sym(g_bfb), *bbb=(float*)sym(g_bbb), *bcb=(float*)sym(g_bcb);
    __nv_bfloat16 *hf_hi=(__nv_bfloat16*)sym(g_hf_hi), *hf_lo=(__nv_bfloat16*)sym(g_hf_lo);
    __nv_bfloat16 *hb_hi=(__nv_bfloat16*)sym(g_hb_hi), *hb_lo=(__nv_bfloat16*)sym(g_hb_lo);
    __nv_bfloat16 *hc_hi=(__nv_bfloat16*)sym(g_hc_hi), *hc_lo=(__nv_bfloat16*)sym(g_hc_lo);
    float *cf=(float*)sym(g_cf), *cb=(float*)sym(g_cb), *cc=(float*)sym(g_cc);

    // 0) split weights, combine biases
    split_pair_kernel<<<512,256>>>(Wih_f, Wihf_hi, Wihf_lo, G4H*HH);
    split_pair_kernel<<<512,256>>>(Whh_f, Whhf_hi, Whhf_lo, G4H*HH);
    split_pair_kernel<<<512,256>>>(Wih_b, Wihb_hi, Wihb_lo, G4H*HH);
    split_pair_kernel<<<512,256>>>(Whh_b, Whhb_hi, Whhb_lo, G4H*HH);
    split_pair_kernel<<<512,256>>>(Wih_c, Wihc_hi, Wihc_lo, G8H*H2);
    split_pair_kernel<<<512,256>>>(Whh_c, Whhc_hi, Whhc_lo, G8H*H2);
    split_pair_kernel<<<2048,256>>>(Wout, Wout_hi, Wout_lo, VV*H2);
    bias_add_kernel<<<(G4H+255)/256,256>>>(bih_f, bhh_f, bfb, G4H);
    bias_add_kernel<<<(G4H+255)/256,256>>>(bih_b, bhh_b, bbb, G4H);
    bias_add_kernel<<<(G8H+255)/256,256>>>(bih_c, bhh_c, bcb, G8H);

    // 1) embedding (raw-reshape) + states (into parity-0 buffers)
    embed_split_kernel<<<SB,128>>>(x, Wemb);
    init_states_kernel<<<(BB*H2+255)/256,256>>>(h0f, c0f, h0b, c0b, h0c, c0c);

    GArgs2 P; GArgs z; memset(&z, 0, sizeof(z));

    // 2) Xf / Xb = seq @ Wih^T + (bih+bhh)
    P.a[0]=z; P.a[0].Ahi=seq_hi; P.a[0].Alo=seq_lo; P.a[0].Bhi=Wihf_hi; P.a[0].Blo=Wihf_lo;
    P.a[0].bias=bfb; P.a[0].C=Xf; P.a[0].ldc=G4H; P.a[0].K=HH; P.a[1]=z;
    mma_gemm<false><<<dim3(G4H/128, SB/128, 1), 256, SMEM_DYN>>>(P);
    P.a[0].Bhi=Wihb_hi; P.a[0].Blo=Wihb_lo; P.a[0].bias=bbb; P.a[0].C=Xb;
    mma_gemm<false><<<dim3(G4H/128, SB/128, 1), 256, SMEM_DYN>>>(P);

    // 3) fwd + bwd recurrence, fused gates (one launch per step, z=2)
    for (int s = 0; s < SS; s++){
        const int rb = s & 1, wb = rb ^ 1;
        GArgs2 Q;
        Q.a[0]=z;
        Q.a[0].Ahi=hf_hi + (size_t)rb*BB*HH; Q.a[0].Alo=hf_lo + (size_t)rb*BB*HH;
        Q.a[0].Bhi=Whhf_hi; Q.a[0].Blo=Whhf_lo;
        Q.a[0].X = Xf + (size_t)s*BB*G4H; Q.a[0].cst=cf;
        Q.a[0].Hhi=hf_hi + (size_t)wb*BB*HH; Q.a[0].Hlo=hf_lo + (size_t)wb*BB*HH;
        Q.a[0].CBhi=cmb_hi; Q.a[0].CBlo=cmb_lo; Q.a[0].combRow=(long)s*BB; Q.a[0].combCol=0;
        Q.a[0].K=HH;
        Q.a[1]=z;
        Q.a[1].Ahi=hb_hi + (size_t)rb*BB*HH; Q.a[1].Alo=hb_lo + (size_t)rb*BB*HH;
        Q.a[1].Bhi=Whhb_hi; Q.a[1].Blo=Whhb_lo;
        Q.a[1].X = Xb + (size_t)(SS-1-s)*BB*G4H; Q.a[1].cst=cb;
        Q.a[1].Hhi=hb_hi + (size_t)wb*BB*HH; Q.a[1].Hlo=hb_lo + (size_t)wb*BB*HH;
        Q.a[1].CBhi=cmb_hi; Q.a[1].CBlo=cmb_lo; Q.a[1].combRow=(long)s*BB; Q.a[1].combCol=HH;
        Q.a[1].K=HH;
        mma_gemm<true><<<dim3(HH/32, BB/128, 2), 256, SMEM_DYN>>>(Q);
    }

    // 4) Xc = comb @ Wih_c^T + (bih_c+bhh_c)
    P.a[0]=z; P.a[0].Ahi=cmb_hi; P.a[0].Alo=cmb_lo; P.a[0].Bhi=Wihc_hi; P.a[0].Blo=Wihc_lo;
    P.a[0].bias=bcb; P.a[0].C=Xc; P.a[0].ldc=G8H; P.a[0].K=H2; P.a[1]=z;
    mma_gemm<false><<<dim3(G8H/128, SB/128, 1), 256, SMEM_DYN>>>(P);

    // 5) combiner recurrence
    for (int s = 0; s < SS; s++){
        const int rb = s & 1, wb = rb ^ 1;
        GArgs2 Q;
        Q.a[0]=z;
        Q.a[0].Ahi=hc_hi + (size_t)rb*BB*H2; Q.a[0].Alo=hc_lo + (size_t)rb*BB*H2;
        Q.a[0].Bhi=Whhc_hi; Q.a[0].Blo=Whhc_lo;
        Q.a[0].X = Xc + (size_t)s*BB*G8H; Q.a[0].cst=cc;
        Q.a[0].Hhi=hc_hi + (size_t)wb*BB*H2; Q.a[0].Hlo=hc_lo + (size_t)wb*BB*H2;
        Q.a[0].CBhi=nullptr; Q.a[0].CBlo=nullptr;
        Q.a[0].K=H2;
        Q.a[1]=z;
        mma_gemm<true><<<dim3(H2/32, BB/128, 1), 256, SMEM_DYN>>>(Q);
    }

    // 6) head: out = hc @ Wout^T + bout  (final h lives in parity-0 buffers: s=63 wrote wb=0)
    P.a[0]=z; P.a[0].Ahi=hc_hi; P.a[0].Alo=hc_lo; P.a[0].Bhi=Wout_hi; P.a[0].Blo=Wout_lo;
    P.a[0].bias=bout; P.a[0].C=out; P.a[0].ldc=VV; P.a[0].K=H2; P.a[1]=z;
    mma_gemm<false><<<dim3(VV/128, BB/128, 1), 256, SMEM_DYN>>>(P);
}